// round 1
// baseline (speedup 1.0000x reference)
#include <cuda_runtime.h>

#define HH 1024
#define WW 1024
#define RMAX 20
#define REG 41                 // 2*RMAX+1
#define CELLS (REG*REG)        // 1681
#define PITCH 48               // padded smem row width
#define SROWS 43               // REG + 2 halo rows
#define GPR 11                 // 4-wide column groups per row: ceil(41/4)
#define NSIM 512

// Scratch for precomputed per-neighbor coefficients and gain (region only).
__device__ float g_coef[8 * CELLS];
__device__ float g_gain[CELLS];

__constant__ int   c_di[8]   = {-1, -1, -1,  0,  0,  1,  1,  1};
__constant__ int   c_dj[8]   = {-1,  0,  1, -1,  1, -1,  0,  1};
__constant__ float c_dist[8] = {0.83f, 1.0f, 0.83f, 1.0f, 1.0f, 0.83f, 1.0f, 0.83f};
__constant__ float c_ui[8]   = {-0.70710678f, -1.0f, -0.70710678f, 0.0f, 0.0f,
                                 0.70710678f,  1.0f,  0.70710678f};
__constant__ float c_uj[8]   = {-0.70710678f,  0.0f,  0.70710678f, -1.0f, 1.0f,
                                -0.70710678f,  0.0f,  0.70710678f};

// ---------------------------------------------------------------------------
// K1: arrival = n_steps everywhere (the sim kernel overwrites the active region)
// ---------------------------------------------------------------------------
__global__ void fill_kernel(float4* __restrict__ out, const int* __restrict__ ns) {
    float v = (float)(*ns);
    int i = blockIdx.x * blockDim.x + threadIdx.x;
    out[i] = make_float4(v, v, v, v);
}

// ---------------------------------------------------------------------------
// K2: per-neighbor coefficient + gain for the 41x41 region around ignition
// ---------------------------------------------------------------------------
__global__ void coef_kernel(const float* __restrict__ height,
                            const float* __restrict__ age,
                            const float* __restrict__ moisture,
                            const float* __restrict__ la, const float* __restrict__ lb,
                            const float* __restrict__ lg, const float* __restrict__ ld,
                            const float* __restrict__ ws, const float* __restrict__ wd,
                            const int*   __restrict__ ip) {
    int idx = blockIdx.x * blockDim.x + threadIdx.x;
    if (idx >= 8 * CELLS) return;
    int k    = idx / CELLS;
    int cell = idx - k * CELLS;
    int r = cell / REG;
    int c = cell - r * REG;
    int gi = ip[0] - RMAX + r;
    int gj = ip[1] - RMAX + c;
    bool ingrid = (gi >= 0) && (gi < HH) && (gj >= 0) && (gj < WW);

    if (k == 0) {
        float g = 0.0f;
        if (ingrid) {
            float alpha = expf(la[0]);
            float beta  = expf(lb[0]);
            float a = age[gi * WW + gj];
            float m = moisture[gi * WW + gj];
            float ratio = fmaxf(a / 30.0f, 1e-6f);               // T_MAX = 30
            float below = exp2f(powf(ratio, alpha)) - 1.0f;      // (1+P_MAX)^(ratio^alpha) - 1
            float af = (a < 30.0f) ? below : 1.0f;               // saturate at P_MAX = 1
            g = af * expf(-beta * m);
        }
        g_gain[cell] = g;
    }

    float coef = 0.0f;
    if (ingrid) {
        int ni = gi + c_di[k];
        int nj = gj + c_dj[k];
        // valid-mask: out-of-grid neighbor contributes 0 (mask), so coef = 0
        if (ni >= 0 && ni < HH && nj >= 0 && nj < WW) {
            float gamma = expf(lg[0]);
            float delta = expf(ld[0]);
            float dh = height[gi * WW + gj] - height[ni * WW + nj];
            float phi = (dh <= 0.0f) ? expf(gamma * dh)
                                     : (1.0f + gamma * sqrtf(dh));
            float s  = ws[ni * WW + nj];
            float dr = wd[ni * WW + nj];
            float wy = s * cosf(dr);
            float wx = s * sinf(dr);
            float align = c_ui[k] * wy + c_uj[k] * wx;
            float wf = fminf(fmaxf(expf(delta * align), -2.0f), 2.0f);
            coef = c_dist[k] * wf * phi;
        }
    }
    g_coef[k * CELLS + cell] = coef;
}

// ---------------------------------------------------------------------------
// K3: full 20-step simulation of the 41x41 light cone in ONE block.
// Coefs/gain/state/arrival live in registers; ping-pong state tile in smem.
// ---------------------------------------------------------------------------
__global__ void __launch_bounds__(NSIM, 1)
sim_kernel(const float* __restrict__ ignv,
           const int*   __restrict__ ip,
           const int*   __restrict__ nsp,
           const int*   __restrict__ nssp,
           float*       __restrict__ out) {
    __shared__ float sbuf[2][SROWS * PITCH];

    int tid = threadIdx.x;
    for (int i = tid; i < 2 * SROWS * PITCH; i += NSIM)
        ((float*)sbuf)[i] = 0.0f;

    int ns  = nsp[0];
    int nss = nssp[0];
    float fns = (float)ns;
    int or0 = ip[0] - RMAX;
    int oc0 = ip[1] - RMAX;

    __syncthreads();
    if (tid == 0)
        sbuf[0][(RMAX + 1) * PITCH + (RMAX + 1)] = ignv[0];  // ignition at region center
    __syncthreads();

    bool active = tid < REG * GPR;  // 451 worker threads
    int row = 0, c0 = 0, cnt = 0;
    if (active) {
        row = tid / GPR;
        c0  = (tid - row * GPR) * 4;
        cnt = min(4, REG - c0);
    }

    float cf[8][4], gn[4], cur[4], prv[4], arr[4];
    #pragma unroll
    for (int i = 0; i < 4; i++) {
        gn[i] = 0.0f; cur[i] = 0.0f; prv[i] = 0.0f; arr[i] = fns;
        #pragma unroll
        for (int k = 0; k < 8; k++) cf[k][i] = 0.0f;
    }
    if (active) {
        for (int i = 0; i < cnt; i++) {
            int cell = row * REG + c0 + i;
            gn[i] = g_gain[cell];
            #pragma unroll
            for (int k = 0; k < 8; k++) cf[k][i] = g_coef[k * CELLS + cell];
            if (row == RMAX && (c0 + i) == RMAX) cur[i] = ignv[0];
        }
    }

    int cb = 0;
    for (int t = 1; t <= ns; t++) {
        for (int s = 0; s < nss; s++) {
            const float* rb = sbuf[cb];
            float*       wb = sbuf[cb ^ 1];
            float nb[3][6];
            #pragma unroll
            for (int dr = 0; dr < 3; dr++)
                #pragma unroll
                for (int dc = 0; dc < 6; dc++)
                    nb[dr][dc] = rb[(row + dr) * PITCH + c0 + dc];
            #pragma unroll
            for (int i = 0; i < 4; i++) {
                float tot = cf[0][i] * nb[0][i]     + cf[1][i] * nb[0][i + 1]
                          + cf[2][i] * nb[0][i + 2] + cf[3][i] * nb[1][i]
                          + cf[4][i] * nb[1][i + 2] + cf[5][i] * nb[2][i]
                          + cf[6][i] * nb[2][i + 1] + cf[7][i] * nb[2][i + 2];
                cur[i] = fminf(fmaxf(cur[i] + gn[i] * tot, 0.0f), 1.0f);
            }
            if (active) {
                for (int i = 0; i < cnt; i++)
                    wb[(row + 1) * PITCH + c0 + 1 + i] = cur[i];
            }
            __syncthreads();
            cb ^= 1;
        }
        float w = fns - (float)t;
        #pragma unroll
        for (int i = 0; i < 4; i++) {
            arr[i] -= fmaxf(cur[i] - prv[i], 0.0f) * w;
            prv[i] = cur[i];
        }
    }

    if (active) {
        for (int i = 0; i < cnt; i++) {
            int gi = or0 + row;
            int gj = oc0 + c0 + i;
            if (gi >= 0 && gi < HH && gj >= 0 && gj < WW)
                out[gi * WW + gj] = arr[i];
        }
    }
}

// ---------------------------------------------------------------------------
extern "C" void kernel_launch(void* const* d_in, const int* in_sizes, int n_in,
                              void* d_out, int out_size) {
    const float* height   = (const float*)d_in[0];
    const float* age      = (const float*)d_in[1];
    const float* moisture = (const float*)d_in[2];
    const float* la       = (const float*)d_in[3];
    const float* lb       = (const float*)d_in[4];
    const float* lg       = (const float*)d_in[5];
    const float* ld       = (const float*)d_in[6];
    const float* ws       = (const float*)d_in[7];
    const float* wd       = (const float*)d_in[8];
    const float* ignv     = (const float*)d_in[9];
    const int*   ip       = (const int*)d_in[10];
    const int*   ns       = (const int*)d_in[11];
    const int*   nss      = (const int*)d_in[12];
    float* out = (float*)d_out;

    // K1: arrival = n_steps everywhere (1M floats as 256K float4 stores)
    fill_kernel<<<(HH * WW / 4) / 256, 256>>>((float4*)out, ns);
    // K2: region coefficients + gain
    coef_kernel<<<(8 * CELLS + 255) / 256, 256>>>(height, age, moisture,
                                                  la, lb, lg, ld, ws, wd, ip);
    // K3: 20-step light-cone simulation, single block
    sim_kernel<<<1, NSIM>>>(ignv, ip, ns, nss, out);
}

// round 2
// speedup vs baseline: 1.3153x; 1.3153x over previous
#include <cuda_runtime.h>

#define HH 1024
#define WW 1024
#define RC 19                  // simulated cone radius (n_steps-1 for n_steps=20)
#define REG 39                 // 2*RC+1
#define CELLS (REG*REG)        // 1521
#define PITCH 48               // padded smem row width (floats), multiple of 4
#define SROWS 41               // REG + 2 halo rows
#define GPR 10                 // 4-wide column groups per row: ceil(39/4)
#define NACT (REG*GPR)         // 390 worker threads
#define NSIM 416               // 13 warps
#define FILLB 512              // fill blocks in fused prep kernel
#define COEFB ((8*CELLS + 255)/256)   // 48

// Scratch for precomputed per-neighbor coefficients and gain (region only).
__device__ float g_coef[8 * CELLS];
__device__ float g_gain[CELLS];

__constant__ int   c_di[8]   = {-1, -1, -1,  0,  0,  1,  1,  1};
__constant__ int   c_dj[8]   = {-1,  0,  1, -1,  1, -1,  0,  1};
__constant__ float c_dist[8] = {0.83f, 1.0f, 0.83f, 1.0f, 1.0f, 0.83f, 1.0f, 0.83f};
__constant__ float c_ui[8]   = {-0.70710678f, -1.0f, -0.70710678f, 0.0f, 0.0f,
                                 0.70710678f,  1.0f,  0.70710678f};
__constant__ float c_uj[8]   = {-0.70710678f,  0.0f,  0.70710678f, -1.0f, 1.0f,
                                -0.70710678f,  0.0f,  0.70710678f};

// ---------------------------------------------------------------------------
// K1 (fused): blocks [0,FILLB) fill the whole output with n_steps;
//             blocks [FILLB, FILLB+COEFB) compute region coefs + gain.
// ---------------------------------------------------------------------------
__global__ void __launch_bounds__(256)
prep_kernel(const float* __restrict__ height,
            const float* __restrict__ age,
            const float* __restrict__ moisture,
            const float* __restrict__ la, const float* __restrict__ lb,
            const float* __restrict__ lg, const float* __restrict__ ld,
            const float* __restrict__ ws, const float* __restrict__ wd,
            const int*   __restrict__ ip,
            const int*   __restrict__ nsp,
            float4*      __restrict__ out4) {
    if (blockIdx.x < FILLB) {
        float v = (float)(*nsp);
        int i = blockIdx.x * 256 + threadIdx.x;   // 131072 threads, 2 float4 each
        float4 f = make_float4(v, v, v, v);
        out4[i] = f;
        out4[i + 131072] = f;
        return;
    }

    int idx = (blockIdx.x - FILLB) * 256 + threadIdx.x;
    if (idx >= 8 * CELLS) return;
    int k    = idx / CELLS;
    int cell = idx - k * CELLS;
    int r = cell / REG;
    int c = cell - r * REG;
    int gi = ip[0] - RC + r;
    int gj = ip[1] - RC + c;
    bool ingrid = (gi >= 0) && (gi < HH) && (gj >= 0) && (gj < WW);

    if (k == 0) {
        float g = 0.0f;
        if (ingrid) {
            float alpha = expf(la[0]);
            float beta  = expf(lb[0]);
            float a = age[gi * WW + gj];
            float m = moisture[gi * WW + gj];
            float ratio = fmaxf(a / 30.0f, 1e-6f);               // T_MAX = 30
            float below = exp2f(powf(ratio, alpha)) - 1.0f;      // (1+P_MAX)^(ratio^alpha) - 1
            float af = (a < 30.0f) ? below : 1.0f;               // saturate at P_MAX = 1
            g = af * expf(-beta * m);
        }
        g_gain[cell] = g;
    }

    float coef = 0.0f;
    if (ingrid) {
        int ni = gi + c_di[k];
        int nj = gj + c_dj[k];
        // valid-mask: out-of-grid neighbor contributes 0 (mask) -> coef = 0
        if (ni >= 0 && ni < HH && nj >= 0 && nj < WW) {
            float gamma = expf(lg[0]);
            float delta = expf(ld[0]);
            float dh = height[gi * WW + gj] - height[ni * WW + nj];
            float phi = (dh <= 0.0f) ? expf(gamma * dh)
                                     : (1.0f + gamma * sqrtf(dh));
            float s  = ws[ni * WW + nj];
            float dr = wd[ni * WW + nj];
            float wy = s * cosf(dr);
            float wx = s * sinf(dr);
            float align = c_ui[k] * wy + c_uj[k] * wx;
            float wf = fminf(fmaxf(expf(delta * align), -2.0f), 2.0f);
            coef = c_dist[k] * wf * phi;
        }
    }
    g_coef[k * CELLS + cell] = coef;
}

// ---------------------------------------------------------------------------
// K2: (n_steps-1)-step simulation of the 39x39 light cone in ONE block.
// Coefs/gain/state/arrival in registers; ping-pong state tile in smem;
// per-step light-cone gating; vectorized LDS/STS.
// Interior cell (r,c) lives at smem[(r+1)*PITCH + c + 4] (16B-aligned groups).
// ---------------------------------------------------------------------------
__global__ void __launch_bounds__(NSIM, 1)
sim_kernel(const float* __restrict__ ignv,
           const int*   __restrict__ ip,
           const int*   __restrict__ nsp,
           const int*   __restrict__ nssp,
           float*       __restrict__ out) {
    __shared__ float sbuf[2][SROWS * PITCH];

    int tid = threadIdx.x;
    for (int i = tid; i < 2 * SROWS * PITCH; i += NSIM)
        ((float*)sbuf)[i] = 0.0f;

    int ns  = nsp[0];
    int nss = nssp[0];
    float fns = (float)ns;
    float ig  = ignv[0];
    int or0 = ip[0] - RC;
    int oc0 = ip[1] - RC;

    __syncthreads();
    if (tid == 0)
        sbuf[0][(RC + 1) * PITCH + (RC + 4)] = ig;   // ignition at region center
    __syncthreads();

    bool worker = tid < NACT;
    int row = 0, c0 = 0, cnt = 0, minrad = 1 << 20;
    if (worker) {
        row = tid / GPR;
        c0  = (tid - row * GPR) * 4;
        cnt = min(4, REG - c0);
        int rrad = abs(row - RC);
        int cmin = (c0 <= RC && RC < c0 + cnt)
                     ? 0 : min(abs(c0 - RC), abs(c0 + cnt - 1 - RC));
        minrad = max(rrad, cmin);
    }

    float cf[8][4], gn[4], cur[4], prv[4], arr[4];
    #pragma unroll
    for (int i = 0; i < 4; i++) {
        gn[i] = 0.0f; cur[i] = 0.0f; prv[i] = 0.0f; arr[i] = fns;
        #pragma unroll
        for (int k = 0; k < 8; k++) cf[k][i] = 0.0f;
    }
    if (worker) {
        for (int i = 0; i < cnt; i++) {
            int cell = row * REG + c0 + i;
            gn[i] = g_gain[cell];
            #pragma unroll
            for (int k = 0; k < 8; k++) cf[k][i] = g_coef[k * CELLS + cell];
            if (row == RC && (c0 + i) == RC) cur[i] = ig;
        }
    }

    int cb = 0;
    for (int t = 1; t < ns; t++) {                 // t = ns has arrival weight 0: skip
        bool act = worker && (t * nss >= minrad);  // light-cone gate
        for (int s = 0; s < nss; s++) {
            if (act) {
                const float* rb = sbuf[cb];
                float*       wb = sbuf[cb ^ 1];
                float tot0 = 0.f, tot1 = 0.f, tot2 = 0.f, tot3 = 0.f;
                #pragma unroll
                for (int dr = 0; dr < 3; dr++) {
                    const float* rp = rb + (row + dr) * PITCH;
                    float  nA = rp[c0 + 3];
                    float4 v  = *(const float4*)(rp + c0 + 4);
                    float  nB = rp[c0 + 8];
                    // n[0..5] = {nA, v.x, v.y, v.z, v.w, nB}; cell i: L=n[i], M=n[i+1], R=n[i+2]
                    if (dr == 0) {
                        tot0 += cf[0][0]*nA  + cf[1][0]*v.x + cf[2][0]*v.y;
                        tot1 += cf[0][1]*v.x + cf[1][1]*v.y + cf[2][1]*v.z;
                        tot2 += cf[0][2]*v.y + cf[1][2]*v.z + cf[2][2]*v.w;
                        tot3 += cf[0][3]*v.z + cf[1][3]*v.w + cf[2][3]*nB;
                    } else if (dr == 1) {
                        tot0 += cf[3][0]*nA  + cf[4][0]*v.y;
                        tot1 += cf[3][1]*v.x + cf[4][1]*v.z;
                        tot2 += cf[3][2]*v.y + cf[4][2]*v.w;
                        tot3 += cf[3][3]*v.z + cf[4][3]*nB;
                    } else {
                        tot0 += cf[5][0]*nA  + cf[6][0]*v.x + cf[7][0]*v.y;
                        tot1 += cf[5][1]*v.x + cf[6][1]*v.y + cf[7][1]*v.z;
                        tot2 += cf[5][2]*v.y + cf[6][2]*v.z + cf[7][2]*v.w;
                        tot3 += cf[5][3]*v.z + cf[6][3]*v.w + cf[7][3]*nB;
                    }
                }
                cur[0] = fminf(fmaxf(cur[0] + gn[0] * tot0, 0.0f), 1.0f);
                cur[1] = fminf(fmaxf(cur[1] + gn[1] * tot1, 0.0f), 1.0f);
                cur[2] = fminf(fmaxf(cur[2] + gn[2] * tot2, 0.0f), 1.0f);
                cur[3] = fminf(fmaxf(cur[3] + gn[3] * tot3, 0.0f), 1.0f);
                // halo-tail lanes have gn=cf=0 -> cur stays 0, safe to store 4-wide
                *(float4*)(sbuf[cb ^ 1] + (row + 1) * PITCH + c0 + 4) =
                    make_float4(cur[0], cur[1], cur[2], cur[3]);
            }
            __syncthreads();
            cb ^= 1;
        }
        float w = fns - (float)t;
        #pragma unroll
        for (int i = 0; i < 4; i++) {
            arr[i] -= fmaxf(cur[i] - prv[i], 0.0f) * w;
            prv[i] = cur[i];
        }
    }

    if (worker) {
        int gi = or0 + row;
        if (gi >= 0 && gi < HH) {
            for (int i = 0; i < cnt; i++) {
                int gj = oc0 + c0 + i;
                if (gj >= 0 && gj < WW)
                    out[gi * WW + gj] = arr[i];
            }
        }
    }
}

// ---------------------------------------------------------------------------
extern "C" void kernel_launch(void* const* d_in, const int* in_sizes, int n_in,
                              void* d_out, int out_size) {
    const float* height   = (const float*)d_in[0];
    const float* age      = (const float*)d_in[1];
    const float* moisture = (const float*)d_in[2];
    const float* la       = (const float*)d_in[3];
    const float* lb       = (const float*)d_in[4];
    const float* lg       = (const float*)d_in[5];
    const float* ld       = (const float*)d_in[6];
    const float* ws       = (const float*)d_in[7];
    const float* wd       = (const float*)d_in[8];
    const float* ignv     = (const float*)d_in[9];
    const int*   ip       = (const int*)d_in[10];
    const int*   ns       = (const int*)d_in[11];
    const int*   nss      = (const int*)d_in[12];
    float* out = (float*)d_out;

    // K1: fused fill (1M floats) + region coefficients/gain
    prep_kernel<<<FILLB + COEFB, 256>>>(height, age, moisture,
                                        la, lb, lg, ld, ws, wd, ip, ns,
                                        (float4*)out);
    // K2: light-cone simulation, single block
    sim_kernel<<<1, NSIM>>>(ignv, ip, ns, nss, out);
}